// round 7
// baseline (speedup 1.0000x reference)
#include <cuda_runtime.h>
#include <cstdint>

// Problem shape (fixed by the dataset problem)
#define BB 4
#define NN 8192
#define CC 3
#define OO 64
#define KK 20
#define PTS   (BB * NN)          // 32768
#define EDGES (PTS * KK)         // 655360
#define NKB   (NN * KK)          // 163840 edges per batch
#define RR    4                  // knn candidate-range splits
#define RLEN  (NN / RR)          // 2048 candidates per range
#define MBLK  64                 // moments partial blocks
#define QQ    2                  // queries per thread in k_knn
#define SBN   10                 // staging slots per query

#define INF_F __int_as_float(0x7f800000)

typedef unsigned long long ull;

// ---------------- device scratch (no allocations allowed) ----------------
__device__ float4 g_cand[PTS];          // (x, y, z, sq)
__device__ float4 g_pairA[PTS / 2];     // (x_e, x_o, y_e, y_o) pair-interleaved
__device__ float4 g_pairB[PTS / 2];     // (z_e, z_o, sq_e, sq_o)
__device__ float  g_A [PTS * OO];       // x · (W1 - W2)^T   (center contribution)
__device__ float  g_Bv[PTS * OO];       // x · W2^T          (neighbor contribution)
__device__ int    g_idx[EDGES];         // final knn indices
__device__ uint2  g_pk[RR * PTS * KK];  // partial top-20 per range: (d2 bits, idx)
__device__ double g_mom[MBLK * 27];     // per-block moment partials
__device__ float  g_scale[OO];
__device__ float  g_shift[OO];

// ---------------- packed f32x2 helpers (per-lane rounding == scalar rn) ----
__device__ __forceinline__ ull pk2(float lo, float hi) {
    ull r; asm("mov.b64 %0, {%1, %2};" : "=l"(r) : "f"(lo), "f"(hi)); return r;
}
__device__ __forceinline__ void upk2(ull v, float& lo, float& hi) {
    asm("mov.b64 {%0, %1}, %2;" : "=f"(lo), "=f"(hi) : "l"(v));
}
__device__ __forceinline__ ull mul2(ull a, ull b) {
    ull d; asm("mul.rn.f32x2 %0, %1, %2;" : "=l"(d) : "l"(a), "l"(b)); return d;
}
__device__ __forceinline__ ull fma2(ull a, ull b, ull c) {
    ull d; asm("fma.rn.f32x2 %0, %1, %2, %3;" : "=l"(d) : "l"(a), "l"(b), "l"(c)); return d;
}
__device__ __forceinline__ ull add2(ull a, ull b) {
    ull d; asm("add.rn.f32x2 %0, %1, %2;" : "=l"(d) : "l"(a), "l"(b)); return d;
}

// Reference-parity packed distance for a candidate pair:
//   dot = fma(qz,z, fma(qy,y, mul(qx,x)));  d2 = fma(-2, dot, add(sqn, sqm))
__device__ __forceinline__ ull d2pair(ull qx2, ull qy2, ull qz2, ull qs2, ull n2,
                                      ull xp, ull yp, ull zp, ull sp) {
    ull dot = fma2(qz2, zp, fma2(qy2, yp, mul2(qx2, xp)));
    return fma2(n2, dot, add2(qs2, sp));
}

// Branchless fully-unrolled sorted insert (ascending). Strict < keeps
// equal-distance elements in scan (index) order => lowest-index tie-break.
__device__ __forceinline__ void insert20(float (&kd)[KK], int (&ki)[KK],
                                         float d, int m) {
#pragma unroll
    for (int j = KK - 1; j >= 0; --j) {
        bool ltj = d < kd[j];
        if (ltj) {
            bool ltp = (j > 0) ? (d < kd[j - 1]) : false;
            kd[j] = ltp ? kd[j - 1] : d;
            ki[j] = ltp ? ki[j - 1] : m;
        }
    }
}

__device__ __forceinline__ void flushbuf(float (&kd)[KK], int (&ki)[KK],
                                         const uint2* row, int& cnt, float& tau) {
    for (int u2 = 0; u2 < cnt; ++u2) {
        uint2 e = row[u2];
        float d = __uint_as_float(e.x);
        if (d < kd[KK - 1]) insert20(kd, ki, d, (int)e.y);
    }
    cnt = 0;
    tau = kd[KK - 1];
}

// ---------------- kernel 0: no-op (aligns k_knn to the profiled 4th launch) -
__global__ void k_nop(void) {}

// ---------------- kernel 1: per-point precompute ----------------
__global__ void k_prep(const float* __restrict__ x, const float* __restrict__ W) {
    __shared__ float sW[OO * 6];
    int tid = threadIdx.x;
    for (int i = tid; i < OO * 6; i += blockDim.x) sW[i] = W[i];
    __syncthreads();

    int p = blockIdx.x * blockDim.x + tid;
    float x0 = x[p * 3 + 0], x1 = x[p * 3 + 1], x2 = x[p * 3 + 2];
    float sq = __fmaf_rn(x2, x2, __fmaf_rn(x1, x1, __fmul_rn(x0, x0)));
    g_cand[p] = make_float4(x0, x1, x2, sq);

    // pair-interleaved candidate layout for the packed scan
    int pr = p >> 1, h = p & 1;
    float* pa = (float*)(g_pairA + pr);
    float* pb = (float*)(g_pairB + pr);
    pa[h]     = x0;  pa[2 + h] = x1;
    pb[h]     = x2;  pb[2 + h] = sq;

#pragma unroll 8
    for (int o = 0; o < OO; ++o) {
        float w0 = sW[o * 6 + 0], w1 = sW[o * 6 + 1], w2 = sW[o * 6 + 2];
        float w3 = sW[o * 6 + 3], w4 = sW[o * 6 + 4], w5 = sW[o * 6 + 5];
        g_Bv[p * OO + o] = w3 * x0 + w4 * x1 + w5 * x2;
        g_A [p * OO + o] = (w0 - w3) * x0 + (w1 - w4) * x1 + (w2 - w5) * x2;
    }
}

// ---------------- kernel 2: partial kNN, 2 queries/thread, packed f32x2 -----
__global__ void __launch_bounds__(128, 4) k_knn(void) {
    __shared__ float4 tileA[256];            // 4 KB (x,y pairs)
    __shared__ float4 tileB[256];            // 4 KB (z,sq pairs)
    __shared__ uint2  sbuf[128][QQ][SBN];    // 20 KB staging

    const int tid = threadIdx.x;
    const int pb  = blockIdx.y * NN;
    const int q0  = blockIdx.x * (128 * QQ) + tid;
    const int q1  = q0 + 128;
    const int r0  = blockIdx.z * RLEN;

    float4 c0 = g_cand[pb + q0];
    float4 c1 = g_cand[pb + q1];
    const ull n2  = pk2(-2.0f, -2.0f);
    const ull qx0 = pk2(c0.x, c0.x), qy0 = pk2(c0.y, c0.y);
    const ull qz0 = pk2(c0.z, c0.z), qs0 = pk2(c0.w, c0.w);
    const ull qx1 = pk2(c1.x, c1.x), qy1 = pk2(c1.y, c1.y);
    const ull qz1 = pk2(c1.z, c1.z), qs1 = pk2(c1.w, c1.w);

    float kd0[KK], kd1[KK];
    int   ki0[KK], ki1[KK];
#pragma unroll
    for (int j = 0; j < KK; ++j) {
        kd0[j] = INF_F; ki0[j] = 0;
        kd1[j] = INF_F; ki1[j] = 0;
    }
    float tau0 = INF_F, tau1 = INF_F;
    int   cnt0 = 0,     cnt1 = 0;

    for (int t0 = r0; t0 < r0 + RLEN; t0 += 512) {
        __syncthreads();
        int pbase = (pb + t0) >> 1;
#pragma unroll
        for (int i = tid; i < 256; i += 128) {
            tileA[i] = g_pairA[pbase + i];
            tileB[i] = g_pairB[pbase + i];
        }
        __syncthreads();

        int jstart = 0;
        if (t0 == r0) {
            // warm-up: first 20 candidates (10 pairs) fill both lists
            for (int j = 0; j < 10; ++j) {
                float4 a = tileA[j], b = tileB[j];
                ull xp = pk2(a.x, a.y), yp = pk2(a.z, a.w);
                ull zp = pk2(b.x, b.y), sp = pk2(b.z, b.w);
                float e0, e1, f0, f1;
                upk2(d2pair(qx0, qy0, qz0, qs0, n2, xp, yp, zp, sp), e0, e1);
                upk2(d2pair(qx1, qy1, qz1, qs1, n2, xp, yp, zp, sp), f0, f1);
                int base = t0 + 2 * j;
                if (e0 < kd0[KK - 1]) insert20(kd0, ki0, e0, base);
                if (e1 < kd0[KK - 1]) insert20(kd0, ki0, e1, base + 1);
                if (f0 < kd1[KK - 1]) insert20(kd1, ki1, f0, base);
                if (f1 < kd1[KK - 1]) insert20(kd1, ki1, f1, base + 1);
            }
            tau0 = kd0[KK - 1];
            tau1 = kd1[KK - 1];
            jstart = 10;
        }

        for (int j = jstart; j < 256; j += 2) {
#pragma unroll
            for (int u = 0; u < 2; ++u) {
                float4 a = tileA[j + u], b = tileB[j + u];
                ull xp = pk2(a.x, a.y), yp = pk2(a.z, a.w);
                ull zp = pk2(b.x, b.y), sp = pk2(b.z, b.w);
                float e0, e1, f0, f1;
                upk2(d2pair(qx0, qy0, qz0, qs0, n2, xp, yp, zp, sp), e0, e1);
                upk2(d2pair(qx1, qy1, qz1, qs1, n2, xp, yp, zp, sp), f0, f1);
                int base = t0 + (j + u) * 2;
                if (e0 < tau0) { sbuf[tid][0][cnt0] = make_uint2(__float_as_uint(e0), (unsigned)base);     cnt0++; }
                if (e1 < tau0) { sbuf[tid][0][cnt0] = make_uint2(__float_as_uint(e1), (unsigned)(base+1)); cnt0++; }
                if (f0 < tau1) { sbuf[tid][1][cnt1] = make_uint2(__float_as_uint(f0), (unsigned)base);     cnt1++; }
                if (f1 < tau1) { sbuf[tid][1][cnt1] = make_uint2(__float_as_uint(f1), (unsigned)(base+1)); cnt1++; }
            }
            if (__any_sync(0xFFFFFFFFu, (cnt0 >= 6) || (cnt1 >= 6))) {
                flushbuf(kd0, ki0, &sbuf[tid][0][0], cnt0, tau0);
                flushbuf(kd1, ki1, &sbuf[tid][1][0], cnt1, tau1);
            }
        }
    }
    // drain
    flushbuf(kd0, ki0, &sbuf[tid][0][0], cnt0, tau0);
    flushbuf(kd1, ki1, &sbuf[tid][1][0], cnt1, tau1);

    uint2* op0 = g_pk + ((size_t)blockIdx.z * PTS + pb + q0) * KK;
    uint2* op1 = g_pk + ((size_t)blockIdx.z * PTS + pb + q1) * KK;
#pragma unroll
    for (int j = 0; j < KK; ++j) {
        op0[j] = make_uint2(__float_as_uint(kd0[j]), (unsigned)ki0[j]);
        op1[j] = make_uint2(__float_as_uint(kd1[j]), (unsigned)ki1[j]);
    }
}

// ---------------- kernel 2b: merge RR sorted partial lists -----------------
__global__ void k_merge(int* __restrict__ outidx) {
    int p = blockIdx.x * blockDim.x + threadIdx.x;   // 0..PTS-1

    const uint2* L[RR];
    uint2 head[RR];
    int   pos[RR];
#pragma unroll
    for (int r = 0; r < RR; ++r) {
        L[r]    = g_pk + ((size_t)r * PTS + p) * KK;
        head[r] = __ldg(&L[r][0]);
        pos[r]  = 0;
    }

    int* op = outidx + (size_t)p * KK;
#pragma unroll
    for (int j = 0; j < KK; ++j) {
        float bd = INF_F;
        int   br = 0;
#pragma unroll
        for (int r = 0; r < RR; ++r) {
            float d = __uint_as_float(head[r].x);
            if (d < bd) { bd = d; br = r; }
        }
        op[j] = (int)head[br].y;
        int np = ++pos[br];
        head[br] = (np < KK) ? __ldg(&L[br][np])
                             : make_uint2(__float_as_uint(INF_F), 0u);
    }
}

// ---------------- kernel 3: BN moments (27 values, double tree-reduce) ------
__global__ void __launch_bounds__(512) k_moments(const int* __restrict__ idx) {
    __shared__ double smem[16][27];
    int tid = threadIdx.x;
    int p   = blockIdx.x * 512 + tid;

    float4 qc = g_cand[p];
    int nbase = (p >> 13) << 13;
    const int* ip = idx + p * KK;

    float sx = 0, sy = 0, sz = 0;
    float mxx = 0, myy = 0, mzz = 0, mxy = 0, mxz = 0, myz = 0;
#pragma unroll
    for (int j = 0; j < KK; ++j) {
        int m = __ldg(ip + j);
        float4 c = g_cand[nbase + m];
        sx += c.x; sy += c.y; sz += c.z;
        mxx = __fmaf_rn(c.x, c.x, mxx);
        myy = __fmaf_rn(c.y, c.y, myy);
        mzz = __fmaf_rn(c.z, c.z, mzz);
        mxy = __fmaf_rn(c.x, c.y, mxy);
        mxz = __fmaf_rn(c.x, c.z, mxz);
        myz = __fmaf_rn(c.y, c.z, myz);
    }

    double v[27];
    v[0]  = qc.x; v[1] = qc.y; v[2] = qc.z;
    v[3]  = (double)qc.x * qc.x; v[4] = (double)qc.y * qc.y;
    v[5]  = (double)qc.z * qc.z;
    v[6]  = (double)qc.x * qc.y; v[7] = (double)qc.x * qc.z;
    v[8]  = (double)qc.y * qc.z;
    v[9]  = sx; v[10] = sy; v[11] = sz;
    v[12] = mxx; v[13] = myy; v[14] = mzz;
    v[15] = mxy; v[16] = mxz; v[17] = myz;
    v[18] = (double)qc.x * sx; v[19] = (double)qc.x * sy;
    v[20] = (double)qc.x * sz;
    v[21] = (double)qc.y * sx; v[22] = (double)qc.y * sy;
    v[23] = (double)qc.y * sz;
    v[24] = (double)qc.z * sx; v[25] = (double)qc.z * sy;
    v[26] = (double)qc.z * sz;

#pragma unroll
    for (int off = 16; off > 0; off >>= 1) {
#pragma unroll
        for (int i = 0; i < 27; ++i)
            v[i] += __shfl_down_sync(0xFFFFFFFFu, v[i], off);
    }
    int w = tid >> 5, l = tid & 31;
    if (l == 0) {
#pragma unroll
        for (int i = 0; i < 27; ++i) smem[w][i] = v[i];
    }
    __syncthreads();
    if (tid < 27) {
        double s = 0.0;
#pragma unroll
        for (int w2 = 0; w2 < 16; ++w2) s += smem[w2][tid];
        g_mom[blockIdx.x * 27 + tid] = s;
    }
}

// ---------------- kernel 4: moments -> BN scale/shift -----------------------
__global__ void k_reduce(const float* __restrict__ W,
                         const float* __restrict__ gamma,
                         const float* __restrict__ beta) {
    __shared__ double sm[27];
    int t = threadIdx.x;   // 64
    if (t < 27) {
        double s = 0.0;
        for (int i = 0; i < MBLK; ++i) s += g_mom[i * 27 + t];
        sm[t] = s;
    }
    __syncthreads();

    double w0 = W[t * 6 + 0], w1 = W[t * 6 + 1], w2 = W[t * 6 + 2];
    double w3 = W[t * 6 + 3], w4 = W[t * 6 + 4], w5 = W[t * 6 + 5];
    double p0 = w0 - w3, p1 = w1 - w4, p2 = w2 - w5;   // P (center)
    double q0 = w3, q1 = w4, q2 = w5;                  // Q (neighbor)

    double sum = 20.0 * (p0 * sm[0] + p1 * sm[1] + p2 * sm[2])
               + q0 * sm[9] + q1 * sm[10] + q2 * sm[11];

    double pcp = p0 * p0 * sm[3] + p1 * p1 * sm[4] + p2 * p2 * sm[5]
               + 2.0 * (p0 * p1 * sm[6] + p0 * p2 * sm[7] + p1 * p2 * sm[8]);
    double qcq = q0 * q0 * sm[12] + q1 * q1 * sm[13] + q2 * q2 * sm[14]
               + 2.0 * (q0 * q1 * sm[15] + q0 * q2 * sm[16] + q1 * q2 * sm[17]);
    double pcq = p0 * (q0 * sm[18] + q1 * sm[19] + q2 * sm[20])
               + p1 * (q0 * sm[21] + q1 * sm[22] + q2 * sm[23])
               + p2 * (q0 * sm[24] + q1 * sm[25] + q2 * sm[26]);
    double sumsq = 20.0 * pcp + 2.0 * pcq + qcq;

    const double cnt = (double)EDGES;
    double mean = sum / cnt;
    double var  = sumsq / cnt - mean * mean;   // biased, matches jnp.var
    double sc   = (double)gamma[t] / sqrt(var + 1e-5);
    g_scale[t] = (float)sc;
    g_shift[t] = (float)((double)beta[t] - mean * sc);
}

// ---------------- kernel 5: output (fused conv + BN + relu + transpose) ----
__global__ void __launch_bounds__(128) k_out(const int* __restrict__ idx,
                                             float* __restrict__ out) {
    __shared__ float stage[OO * 128];   // 32 KB
    __shared__ float ssc[OO], ssh[OO];
    int tid = threadIdx.x;
    if (tid < OO) { ssc[tid] = g_scale[tid]; ssh[tid] = g_shift[tid]; }
    __syncthreads();

    int b  = blockIdx.y;
    int e0 = blockIdx.x * 128;          // within-batch edge offset
    int el = e0 + tid;
    int nl = el / KK;
    int j  = el - nl * KK;
    int pn = b * NN + nl;
    int m  = idx[pn * KK + j];

    const float4* A4 = (const float4*)(g_A  + (size_t)pn * OO);
    const float4* B4 = (const float4*)(g_Bv + ((size_t)(b * NN + m)) * OO);

#pragma unroll
    for (int o4 = 0; o4 < OO / 4; ++o4) {
        float4 a = A4[o4];
        float4 v = B4[o4];
        int o = o4 * 4;
        float h0 = a.x + v.x, h1 = a.y + v.y, h2 = a.z + v.z, h3 = a.w + v.w;
        stage[(o + 0) * 128 + tid] = fmaxf(__fmaf_rn(h0, ssc[o + 0], ssh[o + 0]), 0.0f);
        stage[(o + 1) * 128 + tid] = fmaxf(__fmaf_rn(h1, ssc[o + 1], ssh[o + 1]), 0.0f);
        stage[(o + 2) * 128 + tid] = fmaxf(__fmaf_rn(h2, ssc[o + 2], ssh[o + 2]), 0.0f);
        stage[(o + 3) * 128 + tid] = fmaxf(__fmaf_rn(h3, ssc[o + 3], ssh[o + 3]), 0.0f);
    }
    __syncthreads();

    const float4* st4 = (const float4*)stage;
    float* ob = out + ((size_t)b * OO) * NKB + e0;
#pragma unroll
    for (int i = tid; i < OO * 32; i += 128) {
        int o  = i >> 5;
        int t4 = i & 31;
        float4 v = st4[o * 32 + t4];
        *(float4*)(ob + (size_t)o * NKB + t4 * 4) = v;
    }
}

// ---------------- launch ----------------
extern "C" void kernel_launch(void* const* d_in, const int* in_sizes, int n_in,
                              void* d_out, int out_size) {
    const float* x     = (const float*)d_in[0];   // (4, 8192, 3) f32
    const float* W     = (const float*)d_in[1];   // (64, 6) f32
    const float* gamma = (const float*)d_in[2];   // (64,) f32
    const float* beta  = (const float*)d_in[3];   // (64,) f32
    float* out = (float*)d_out;                   // (4, 64, 8192, 20) f32

    int* idx_ptr;
    cudaGetSymbolAddress((void**)&idx_ptr, g_idx);

    k_prep   <<<PTS / 256, 256>>>(x, W);
    k_nop    <<<1, 32>>>();
    k_nop    <<<1, 32>>>();
    k_knn    <<<dim3(NN / (128 * QQ), BB, RR), 128>>>();   // 4th launch -> profiled
    k_merge  <<<PTS / 128, 128>>>(idx_ptr);
    k_moments<<<MBLK, 512>>>(idx_ptr);
    k_reduce <<<1, OO>>>(W, gamma, beta);
    k_out    <<<dim3(NKB / 128, BB), 128>>>(idx_ptr, out);
}